// round 1
// baseline (speedup 1.0000x reference)
#include <cuda_runtime.h>

#define B_ 8
#define H_ 128
#define W_ 128
#define C_ 256
#define OC_ 512
#define KTOT_ 2304   // 9 * 256
#define NTILES_ 144  // KTOT_ / 16

// Scratch for conv output (offsets): 8*128*128*512 floats = 268 MB
__device__ float g_off[(size_t)B_ * H_ * W_ * OC_];

// ---------------------------------------------------------------------------
// Conv 3x3 SAME, NHWC x HWIO -> NHWC, as implicit GEMM.
// Block tile: 128 positions (one full image row) x 128 out-channels, BK=16.
// 256 threads, each computes 8x8 fp32 accumulators. Double-buffered smem.
// ---------------------------------------------------------------------------

__device__ __forceinline__ void load_A(const float* __restrict__ x,
                                       int b, int i, int tid, int kt,
                                       float4 ar[2]) {
    const int tap = kt >> 4;           // 0..8
    const int di  = tap / 3;
    const int dj  = tap - di * 3;
    const int ii  = i + di - 1;
    const int ic0 = (kt & 15) * 16;
    const float* xbase = x + (size_t)b * (H_ * W_ * C_);
#pragma unroll
    for (int r = 0; r < 2; r++) {
        const int idx = tid + 256 * r;
        const int ml  = idx >> 2;          // position j within row: 0..127
        const int kq  = (idx & 3) * 4;     // ic sub-offset: 0,4,8,12
        const int jj  = ml + dj - 1;
        float4 v = make_float4(0.f, 0.f, 0.f, 0.f);
        if ((unsigned)ii < H_ && (unsigned)jj < W_) {
            v = *(const float4*)(xbase + ((size_t)ii * W_ + jj) * C_ + ic0 + kq);
        }
        ar[r] = v;
    }
}

__device__ __forceinline__ void load_B(const float* __restrict__ wgt,
                                       int n0, int tid, int kt,
                                       float4 br[2]) {
    const int k0 = kt * 16;
#pragma unroll
    for (int r = 0; r < 2; r++) {
        const int idx = tid + 256 * r;
        const int kk  = idx >> 5;          // 0..15
        const int n4  = (idx & 31) * 4;    // 0..124
        br[r] = *(const float4*)(wgt + (size_t)(k0 + kk) * OC_ + n0 + n4);
    }
}

__global__ __launch_bounds__(256, 2)
void conv3x3_kernel(const float* __restrict__ x,
                    const float* __restrict__ wgt,
                    const float* __restrict__ bias) {
    __shared__ float As[2][16][128];   // [buf][k][m]
    __shared__ float Bs[2][16][128];   // [buf][k][n]

    const int mt  = blockIdx.y;        // row-tile: 0..1023
    const int n0  = blockIdx.x * 128;  // out-channel tile: 0..3 * 128
    const int b   = mt >> 7;
    const int i   = mt & 127;
    const int tid = threadIdx.x;
    const int ty  = tid >> 4;
    const int tx  = tid & 15;

    float acc[8][8] = {};
    float4 ar[2], br[2];

    // Prologue: load tile 0
    load_A(x, b, i, tid, 0, ar);
    load_B(wgt, n0, tid, 0, br);
#pragma unroll
    for (int r = 0; r < 2; r++) {
        const int idx = tid + 256 * r;
        const int ml  = idx >> 2;
        const int kq  = (idx & 3) * 4;
        As[0][kq + 0][ml] = ar[r].x;
        As[0][kq + 1][ml] = ar[r].y;
        As[0][kq + 2][ml] = ar[r].z;
        As[0][kq + 3][ml] = ar[r].w;
        const int kk = idx >> 5;
        const int n4 = (idx & 31) * 4;
        *(float4*)&Bs[0][kk][n4] = br[r];
    }
    __syncthreads();

    for (int kt = 0; kt < NTILES_; kt++) {
        const int cb = kt & 1;
        if (kt + 1 < NTILES_) {
            load_A(x, b, i, tid, kt + 1, ar);
            load_B(wgt, n0, tid, kt + 1, br);
        }
#pragma unroll
        for (int kk = 0; kk < 16; kk++) {
            float a[8], bb[8];
            *(float4*)&a[0]  = *(const float4*)&As[cb][kk][ty * 8];
            *(float4*)&a[4]  = *(const float4*)&As[cb][kk][ty * 8 + 4];
            *(float4*)&bb[0] = *(const float4*)&Bs[cb][kk][tx * 8];
            *(float4*)&bb[4] = *(const float4*)&Bs[cb][kk][tx * 8 + 4];
#pragma unroll
            for (int u = 0; u < 8; u++)
#pragma unroll
                for (int v = 0; v < 8; v++)
                    acc[u][v] = fmaf(a[u], bb[v], acc[u][v]);
        }
        if (kt + 1 < NTILES_) {
            const int nb = cb ^ 1;
#pragma unroll
            for (int r = 0; r < 2; r++) {
                const int idx = tid + 256 * r;
                const int ml  = idx >> 2;
                const int kq  = (idx & 3) * 4;
                As[nb][kq + 0][ml] = ar[r].x;
                As[nb][kq + 1][ml] = ar[r].y;
                As[nb][kq + 2][ml] = ar[r].z;
                As[nb][kq + 3][ml] = ar[r].w;
                const int kk = idx >> 5;
                const int n4 = (idx & 31) * 4;
                *(float4*)&Bs[nb][kk][n4] = br[r];
            }
        }
        __syncthreads();
    }

    // Epilogue: offsets = conv + bias
    const size_t row_base = (size_t)mt * 128 * OC_;
    float bvals[8];
#pragma unroll
    for (int v = 0; v < 8; v++) bvals[v] = bias[n0 + tx * 8 + v];
#pragma unroll
    for (int u = 0; u < 8; u++) {
        const int m = ty * 8 + u;
        float* op = g_off + row_base + (size_t)m * OC_ + n0 + tx * 8;
        float4 o0, o1;
        o0.x = acc[u][0] + bvals[0];
        o0.y = acc[u][1] + bvals[1];
        o0.z = acc[u][2] + bvals[2];
        o0.w = acc[u][3] + bvals[3];
        o1.x = acc[u][4] + bvals[4];
        o1.y = acc[u][5] + bvals[5];
        o1.z = acc[u][6] + bvals[6];
        o1.w = acc[u][7] + bvals[7];
        *(float4*)(op)     = o0;
        *(float4*)(op + 4) = o1;
    }
}

// ---------------------------------------------------------------------------
// Deformable sampling with keras-reshape remap.
// For output (b,i,j,q):
//   delta = (i >= 64), i' = 2*(i&63) + (j>=64), j0 = (2j)&127
//   off_t = conv[b, i', j0 + t, 2q + delta]   (t = 0,1)
//   coord0 = clip(off0 + i, 0, 127); coord1 = clip(off1 + j, 0, 127)
//   bilinear sample of x[b, :, :, q] (with floor/ceil corners).
// ---------------------------------------------------------------------------
__global__ void sample_kernel(const float* __restrict__ x,
                              float* __restrict__ out) {
    const int bij = blockIdx.x;      // 0 .. B*H*W-1
    const int q   = threadIdx.x;     // 0 .. 255
    const int j   = bij & 127;
    const int i   = (bij >> 7) & 127;
    const int b   = bij >> 14;

    const int delta = (i >= 64) ? 1 : 0;
    const int ip    = 2 * (i & 63) + ((j >= 64) ? 1 : 0);
    const int jp0   = (2 * j) & 127;

    const float* orow =
        g_off + (((size_t)(b * H_ + ip)) * W_ + jp0) * OC_ + 2 * q + delta;
    const float off0 = orow[0];
    const float off1 = orow[OC_];    // next column, same channel

    float c0 = off0 + (float)i;
    float c1 = off1 + (float)j;
    c0 = fminf(fmaxf(c0, 0.f), (float)(W_ - 1));
    c1 = fminf(fmaxf(c1, 0.f), (float)(H_ - 1));

    const float fl0 = floorf(c0), fl1 = floorf(c1);
    const int lt0 = (int)fl0,        lt1 = (int)fl1;
    const int rb0 = (int)ceilf(c0),  rb1 = (int)ceilf(c1);
    const float fr0 = c0 - fl0, fr1 = c1 - fl1;

    const float* xb = x + (size_t)b * (H_ * W_ * C_) + q;
    const float v_lt = xb[(size_t)(lt0 * W_ + lt1) * C_];
    const float v_rb = xb[(size_t)(rb0 * W_ + rb1) * C_];
    const float v_lb = xb[(size_t)(lt0 * W_ + rb1) * C_];
    const float v_rt = xb[(size_t)(rb0 * W_ + lt1) * C_];

    const float vt = v_lt + (v_rt - v_lt) * fr0;
    const float vb = v_lb + (v_rb - v_lb) * fr0;
    out[(size_t)bij * C_ + q] = vt + (vb - vt) * fr1;
}

extern "C" void kernel_launch(void* const* d_in, const int* in_sizes, int n_in,
                              void* d_out, int out_size) {
    const float* x    = (const float*)d_in[0];   // (8,128,128,256) f32
    const float* wgt  = (const float*)d_in[1];   // (3,3,256,512)  f32
    const float* bias = (const float*)d_in[2];   // (512,)         f32
    float* out = (float*)d_out;                  // (8,128,128,256) f32

    dim3 cgrid(OC_ / 128, (B_ * H_));            // (4, 1024)
    conv3x3_kernel<<<cgrid, 256>>>(x, wgt, bias);

    sample_kernel<<<B_ * H_ * W_, 256>>>(x, out);
}

// round 3
// speedup vs baseline: 6.2915x; 6.2915x over previous
#include <cuda_runtime.h>
#include <cuda_fp16.h>
#include <cstdint>

#define B_ 8
#define H_ 128
#define W_ 128
#define C_ 256
#define OC_ 512
#define KTOT_ 2304   // 9 taps * 256

// ---------------- static device scratch (no allocs) ----------------
__device__ float g_off[(size_t)B_ * H_ * W_ * OC_];                 // conv out
__device__ __align__(16) __half g_xh[(size_t)B_ * H_ * W_ * C_];    // x in f16
__device__ __align__(16) __half g_wT[(size_t)OC_ * KTOT_];          // W^T [n][k] f16

// ---------------- helpers ----------------
__device__ __forceinline__ uint32_t smem_u32(const void* p) {
    uint32_t a;
    asm("{ .reg .u64 t; cvta.to.shared.u64 t, %1; cvt.u32.u64 %0, t; }"
        : "=r"(a) : "l"(p));
    return a;
}

#define CP16(dst, src, sz) \
    asm volatile("cp.async.cg.shared.global [%0], [%1], 16, %2;" \
                 :: "r"(dst), "l"(src), "r"(sz))
#define CP_COMMIT() asm volatile("cp.async.commit_group;" ::: "memory")

#define LDSM4(r0, r1, r2, r3, a) \
    asm volatile("ldmatrix.sync.aligned.m8n8.x4.shared.b16 {%0,%1,%2,%3}, [%4];" \
                 : "=r"(r0), "=r"(r1), "=r"(r2), "=r"(r3) : "r"(a))

#define MMA16816(c, a, b0, b1) \
    asm volatile("mma.sync.aligned.m16n8k16.row.col.f32.f16.f16.f32 " \
                 "{%0,%1,%2,%3}, {%4,%5,%6,%7}, {%8,%9}, {%0,%1,%2,%3};" \
                 : "+f"((c)[0]), "+f"((c)[1]), "+f"((c)[2]), "+f"((c)[3]) \
                 : "r"((a)[0]), "r"((a)[1]), "r"((a)[2]), "r"((a)[3]), \
                   "r"(b0), "r"(b1))

// ---------------- fp32 -> fp16 conversion kernels ----------------
__global__ void __launch_bounds__(256) conv_x_f16(const float* __restrict__ x) {
    const size_t i = (size_t)blockIdx.x * 256 + threadIdx.x;  // per 8 floats
    const float4* xv = (const float4*)x;
    float4 v0 = xv[i * 2], v1 = xv[i * 2 + 1];
    __half2 h0 = __floats2half2_rn(v0.x, v0.y);
    __half2 h1 = __floats2half2_rn(v0.z, v0.w);
    __half2 h2 = __floats2half2_rn(v1.x, v1.y);
    __half2 h3 = __floats2half2_rn(v1.z, v1.w);
    uint4 o;
    o.x = *reinterpret_cast<uint32_t*>(&h0);
    o.y = *reinterpret_cast<uint32_t*>(&h1);
    o.z = *reinterpret_cast<uint32_t*>(&h2);
    o.w = *reinterpret_cast<uint32_t*>(&h3);
    ((uint4*)g_xh)[i] = o;
}

__global__ void __launch_bounds__(256) conv_w_f16(const float* __restrict__ w) {
    const int idx = blockIdx.x * 256 + threadIdx.x;  // 512 * 288 = 147456
    const int n  = idx / 288;
    const int kc = idx - n * 288;
    __align__(16) __half h[8];
#pragma unroll
    for (int t = 0; t < 8; ++t)
        h[t] = __float2half_rn(w[(size_t)(kc * 8 + t) * OC_ + n]);
    *(uint4*)(g_wT + (size_t)n * KTOT_ + kc * 8) = *(const uint4*)h;
}

// ---------------- HMMA implicit-GEMM conv ----------------
// CTA: M=128 (one image row), N=128, K-chunk=32, 72 iters, double-buffered.
// smem rows padded 32->40 halfs (80B): conflict-free ldmatrix, no swizzle.
__global__ void __launch_bounds__(256, 2)
conv_hmma(const float* __restrict__ bias) {
    __shared__ __align__(16) __half As[2][128][40];
    __shared__ __align__(16) __half Bs[2][128][40];

    const int tid  = threadIdx.x;
    const int mt   = blockIdx.y;          // b*128 + image row i
    const int n0   = blockIdx.x * 128;    // out-channel tile
    const int b    = mt >> 7;
    const int irow = mt & 127;
    const __half* xb = g_xh + (size_t)b * (H_ * W_ * C_);

    auto load_stage = [&](int st, int kt) {
        const int tap = kt >> 3;                  // k-chunk 32 -> 8 chunks/tap
        const int di  = tap / 3;
        const int dj  = tap - 3 * di;
        const int ii  = irow + di - 1;
        const bool rowok = ((unsigned)ii < 128u);
        const int c0  = (kt & 7) * 32;
#pragma unroll
        for (int it = 0; it < 2; ++it) {
            const int ch = it * 256 + tid;        // 0..511
            const int r  = ch >> 2;
            const int kc = ch & 3;
            // A (im2col of x, zero-filled halo via src-size 0)
            const int jj = r + dj - 1;
            const __half* ga = xb;
            int sz = 0;
            if (rowok && (unsigned)jj < 128u) {
                ga = xb + ((size_t)ii * 128 + jj) * 256 + c0 + kc * 8;
                sz = 16;
            }
            CP16(smem_u32(&As[st][r][kc * 8]), ga, sz);
            // B (W^T[n][k])
            const __half* gb = g_wT + (size_t)(n0 + r) * KTOT_ + kt * 32 + kc * 8;
            CP16(smem_u32(&Bs[st][r][kc * 8]), gb, 16);
        }
        CP_COMMIT();
    };

    load_stage(0, 0);
    load_stage(1, 1);

    const int warp = tid >> 5;
    const int lane = tid & 31;
    const int wm = (warp >> 2) * 64;   // warp M offset
    const int wn = (warp & 3) * 32;    // warp N offset

    float acc[4][4][4] = {};

    for (int kt = 0; kt < 72; ++kt) {
        const int s = kt & 1;
        if (kt < 71) asm volatile("cp.async.wait_group 1;" ::: "memory");
        else         asm volatile("cp.async.wait_group 0;" ::: "memory");
        __syncthreads();

#pragma unroll
        for (int ks = 0; ks < 2; ++ks) {
            uint32_t a[4][4], bf[2][4];
#pragma unroll
            for (int mf = 0; mf < 4; ++mf)
                LDSM4(a[mf][0], a[mf][1], a[mf][2], a[mf][3],
                      smem_u32(&As[s][wm + mf * 16 + (lane & 15)]
                                     [ks * 16 + (lane >> 4) * 8]));
#pragma unroll
            for (int nf2 = 0; nf2 < 2; ++nf2)
                LDSM4(bf[nf2][0], bf[nf2][1], bf[nf2][2], bf[nf2][3],
                      smem_u32(&Bs[s][wn + nf2 * 16 + (lane & 7) + ((lane >> 4) << 3)]
                                     [ks * 16 + ((lane >> 3) & 1) * 8]));
#pragma unroll
            for (int mf = 0; mf < 4; ++mf)
#pragma unroll
                for (int nf = 0; nf < 4; ++nf)
                    MMA16816(acc[mf][nf], a[mf],
                             bf[nf >> 1][(nf & 1) * 2],
                             bf[nf >> 1][(nf & 1) * 2 + 1]);
        }
        __syncthreads();
        if (kt + 2 < 72) load_stage(s, kt + 2);
    }
    asm volatile("cp.async.wait_all;" ::: "memory");

    // epilogue: + bias, write fp32 offsets
    const size_t rowbase = (size_t)mt * 128 * OC_;
#pragma unroll
    for (int mf = 0; mf < 4; ++mf) {
        const int m0 = wm + mf * 16 + (lane >> 2);
#pragma unroll
        for (int nf = 0; nf < 4; ++nf) {
            const int col = n0 + wn + nf * 8 + (lane & 3) * 2;
            const float b0v = bias[col], b1v = bias[col + 1];
            float2 v0 = make_float2(acc[mf][nf][0] + b0v, acc[mf][nf][1] + b1v);
            float2 v1 = make_float2(acc[mf][nf][2] + b0v, acc[mf][nf][3] + b1v);
            *(float2*)(g_off + rowbase + (size_t)m0 * OC_ + col)       = v0;
            *(float2*)(g_off + rowbase + (size_t)(m0 + 8) * OC_ + col) = v1;
        }
    }
}

// ---------------- deformable sampling (keras reshape remap) ----------------
__global__ void sample_kernel(const float* __restrict__ x,
                              float* __restrict__ out) {
    const int bij = blockIdx.x;
    const int q   = threadIdx.x;
    const int j   = bij & 127;
    const int i   = (bij >> 7) & 127;
    const int b   = bij >> 14;

    const int delta = (i >= 64) ? 1 : 0;
    const int ip    = 2 * (i & 63) + ((j >= 64) ? 1 : 0);
    const int jp0   = (2 * j) & 127;

    const float* orow =
        g_off + (((size_t)(b * H_ + ip)) * W_ + jp0) * OC_ + 2 * q + delta;
    const float off0 = orow[0];
    const float off1 = orow[OC_];

    float c0 = off0 + (float)i;
    float c1 = off1 + (float)j;
    c0 = fminf(fmaxf(c0, 0.f), (float)(W_ - 1));
    c1 = fminf(fmaxf(c1, 0.f), (float)(H_ - 1));

    const float fl0 = floorf(c0), fl1 = floorf(c1);
    const int lt0 = (int)fl0,       lt1 = (int)fl1;
    const int rb0 = (int)ceilf(c0), rb1 = (int)ceilf(c1);
    const float fr0 = c0 - fl0, fr1 = c1 - fl1;

    const float* xp = x + (size_t)b * (H_ * W_ * C_) + q;
    const float v_lt = xp[(size_t)(lt0 * W_ + lt1) * C_];
    const float v_rb = xp[(size_t)(rb0 * W_ + rb1) * C_];
    const float v_lb = xp[(size_t)(lt0 * W_ + rb1) * C_];
    const float v_rt = xp[(size_t)(rb0 * W_ + lt1) * C_];

    const float vt = v_lt + (v_rt - v_lt) * fr0;
    const float vb = v_lb + (v_rb - v_lb) * fr0;
    out[(size_t)bij * C_ + q] = vt + (vb - vt) * fr1;
}

// ---------------- launch ----------------
extern "C" void kernel_launch(void* const* d_in, const int* in_sizes, int n_in,
                              void* d_out, int out_size) {
    const float* x    = (const float*)d_in[0];   // (8,128,128,256) f32
    const float* wgt  = (const float*)d_in[1];   // (3,3,256,512)  f32
    const float* bias = (const float*)d_in[2];   // (512,)         f32
    float* out = (float*)d_out;

    conv_x_f16<<<16384, 256>>>(x);               // 33.5M halfs / 8 per thread
    conv_w_f16<<<576, 256>>>(wgt);               // 147456 threads

    conv_hmma<<<dim3(4, 1024), 256>>>(bias);

    sample_kernel<<<B_ * H_ * W_, 256>>>(x, out);
}

// round 4
// speedup vs baseline: 6.7971x; 1.0804x over previous
#include <cuda_runtime.h>
#include <cuda_fp16.h>
#include <cstdint>

#define B_ 8
#define H_ 128
#define W_ 128
#define C_ 256
#define OC_ 512
#define KTOT_ 2304   // 9 taps * 256
#define S_ 3         // pipeline stages

// ---------------- static device scratch (no allocs) ----------------
__device__ __align__(16) __half g_off[(size_t)B_ * H_ * W_ * OC_];  // conv out (fp16)
__device__ __align__(16) __half g_xh[(size_t)B_ * H_ * W_ * C_];    // x in f16
__device__ __align__(16) __half g_wT[(size_t)OC_ * KTOT_];          // W^T [n][k] f16

// ---------------- helpers ----------------
__device__ __forceinline__ uint32_t smem_u32(const void* p) {
    uint32_t a;
    asm("{ .reg .u64 t; cvta.to.shared.u64 t, %1; cvt.u32.u64 %0, t; }"
        : "=r"(a) : "l"(p));
    return a;
}

#define CP16(dst, src, sz) \
    asm volatile("cp.async.cg.shared.global [%0], [%1], 16, %2;" \
                 :: "r"(dst), "l"(src), "r"(sz))
#define CP_COMMIT() asm volatile("cp.async.commit_group;" ::: "memory")

#define LDSM4(r0, r1, r2, r3, a) \
    asm volatile("ldmatrix.sync.aligned.m8n8.x4.shared.b16 {%0,%1,%2,%3}, [%4];" \
                 : "=r"(r0), "=r"(r1), "=r"(r2), "=r"(r3) : "r"(a))

#define MMA16816(c, a, b0, b1) \
    asm volatile("mma.sync.aligned.m16n8k16.row.col.f32.f16.f16.f32 " \
                 "{%0,%1,%2,%3}, {%4,%5,%6,%7}, {%8,%9}, {%0,%1,%2,%3};" \
                 : "+f"((c)[0]), "+f"((c)[1]), "+f"((c)[2]), "+f"((c)[3]) \
                 : "r"((a)[0]), "r"((a)[1]), "r"((a)[2]), "r"((a)[3]), \
                   "r"(b0), "r"(b1))

// ---------------- fp32 -> fp16 conversion kernels ----------------
__global__ void __launch_bounds__(256) conv_x_f16(const float* __restrict__ x) {
    const size_t i = (size_t)blockIdx.x * 256 + threadIdx.x;  // per 8 floats
    const float4* xv = (const float4*)x;
    float4 v0 = xv[i * 2], v1 = xv[i * 2 + 1];
    __half2 h0 = __floats2half2_rn(v0.x, v0.y);
    __half2 h1 = __floats2half2_rn(v0.z, v0.w);
    __half2 h2 = __floats2half2_rn(v1.x, v1.y);
    __half2 h3 = __floats2half2_rn(v1.z, v1.w);
    uint4 o;
    o.x = *reinterpret_cast<uint32_t*>(&h0);
    o.y = *reinterpret_cast<uint32_t*>(&h1);
    o.z = *reinterpret_cast<uint32_t*>(&h2);
    o.w = *reinterpret_cast<uint32_t*>(&h3);
    ((uint4*)g_xh)[i] = o;
}

__global__ void __launch_bounds__(256) conv_w_f16(const float* __restrict__ w) {
    const int idx = blockIdx.x * 256 + threadIdx.x;  // 512 * 288 = 147456
    const int n  = idx / 288;
    const int kc = idx - n * 288;
    __align__(16) __half h[8];
#pragma unroll
    for (int t = 0; t < 8; ++t)
        h[t] = __float2half_rn(w[(size_t)(kc * 8 + t) * OC_ + n]);
    *(uint4*)(g_wT + (size_t)n * KTOT_ + kc * 8) = *(const uint4*)h;
}

// ---------------- HMMA implicit-GEMM conv ----------------
// CTA: M=128 (one image row), N=128, K-chunk=32, 72 iters.
// 3-stage cp.async ring, ONE __syncthreads per iteration.
// smem rows padded 32->40 halfs (80B): conflict-free ldmatrix.
#define A_IDX(st, r, c) (((st) * 128 + (r)) * 40 + (c))
#define SMEM_HALFS (S_ * 128 * 40)           // per array
#define SMEM_BYTES (2 * SMEM_HALFS * 2)      // A + B, fp16

__global__ void __launch_bounds__(256, 2)
conv_hmma(const float* __restrict__ bias) {
    extern __shared__ __half sm[];
    __half* As = sm;
    __half* Bs = sm + SMEM_HALFS;

    const int tid  = threadIdx.x;
    const int mt   = blockIdx.y;          // b*128 + image row i
    const int n0   = blockIdx.x * 128;    // out-channel tile
    const int b    = mt >> 7;
    const int irow = mt & 127;
    const __half* xb = g_xh + (size_t)b * (H_ * W_ * C_);

    auto load_stage = [&](int st, int kt) {
        if (kt < 72) {
            const int tap = kt >> 3;              // 8 k-chunks per tap
            const int di  = tap / 3;
            const int dj  = tap - 3 * di;
            const int ii  = irow + di - 1;
            const bool rowok = ((unsigned)ii < 128u);
            const int c0  = (kt & 7) * 32;
#pragma unroll
            for (int it = 0; it < 2; ++it) {
                const int ch = it * 256 + tid;    // 0..511
                const int r  = ch >> 2;
                const int kc = ch & 3;
                // A (im2col of x, zero-filled halo via src-size 0)
                const int jj = r + dj - 1;
                const __half* ga = xb;
                int sz = 0;
                if (rowok && (unsigned)jj < 128u) {
                    ga = xb + ((size_t)ii * 128 + jj) * 256 + c0 + kc * 8;
                    sz = 16;
                }
                CP16(smem_u32(&As[A_IDX(st, r, kc * 8)]), ga, sz);
                // B (W^T[n][k])
                const __half* gb = g_wT + (size_t)(n0 + r) * KTOT_ + kt * 32 + kc * 8;
                CP16(smem_u32(&Bs[A_IDX(st, r, kc * 8)]), gb, 16);
            }
        }
        CP_COMMIT();   // commit even when empty: keeps group accounting uniform
    };

    load_stage(0, 0);
    load_stage(1, 1);

    const int warp = tid >> 5;
    const int lane = tid & 31;
    const int wm = (warp >> 2) * 64;   // warp M offset
    const int wn = (warp & 3) * 32;    // warp N offset

    float acc[4][4][4] = {};

    for (int kt = 0; kt < 72; ++kt) {
        const int s = kt % S_;
        asm volatile("cp.async.wait_group 1;" ::: "memory");  // stage kt ready
        __syncthreads();                                       // + iter kt-1 compute done
        load_stage((kt + 2) % S_, kt + 2);                     // overlap with MMAs below

#pragma unroll
        for (int ks = 0; ks < 2; ++ks) {
            uint32_t a[4][4], bf[2][4];
#pragma unroll
            for (int mf = 0; mf < 4; ++mf)
                LDSM4(a[mf][0], a[mf][1], a[mf][2], a[mf][3],
                      smem_u32(&As[A_IDX(s, wm + mf * 16 + (lane & 15),
                                         ks * 16 + (lane >> 4) * 8)]));
#pragma unroll
            for (int nf2 = 0; nf2 < 2; ++nf2)
                LDSM4(bf[nf2][0], bf[nf2][1], bf[nf2][2], bf[nf2][3],
                      smem_u32(&Bs[A_IDX(s, wn + nf2 * 16 + (lane & 7) + ((lane >> 4) << 3),
                                         ks * 16 + ((lane >> 3) & 1) * 8)]));
#pragma unroll
            for (int mf = 0; mf < 4; ++mf)
#pragma unroll
                for (int nf = 0; nf < 4; ++nf)
                    MMA16816(acc[mf][nf], a[mf],
                             bf[nf >> 1][(nf & 1) * 2],
                             bf[nf >> 1][(nf & 1) * 2 + 1]);
        }
    }

    // epilogue: + bias, write fp16 offsets
    const size_t rowbase = (size_t)mt * 128 * OC_;
#pragma unroll
    for (int mf = 0; mf < 4; ++mf) {
        const int m0 = wm + mf * 16 + (lane >> 2);
#pragma unroll
        for (int nf = 0; nf < 4; ++nf) {
            const int col = n0 + wn + nf * 8 + (lane & 3) * 2;
            const float b0v = bias[col], b1v = bias[col + 1];
            __half2 v0 = __floats2half2_rn(acc[mf][nf][0] + b0v, acc[mf][nf][1] + b1v);
            __half2 v1 = __floats2half2_rn(acc[mf][nf][2] + b0v, acc[mf][nf][3] + b1v);
            *(uint32_t*)(g_off + rowbase + (size_t)m0 * OC_ + col) =
                *reinterpret_cast<uint32_t*>(&v0);
            *(uint32_t*)(g_off + rowbase + (size_t)(m0 + 8) * OC_ + col) =
                *reinterpret_cast<uint32_t*>(&v1);
        }
    }
}

// ---------------- deformable sampling (keras reshape remap) ----------------
// Two spatial positions per block -> 2 independent load chains per thread (MLP x2).
__device__ __forceinline__ float sample_one(const float* __restrict__ x,
                                            int b, int i, int j, int q) {
    const int delta = (i >= 64) ? 1 : 0;
    const int ip    = 2 * (i & 63) + ((j >= 64) ? 1 : 0);
    const int jp0   = (2 * j) & 127;

    const __half* orow =
        g_off + (((size_t)(b * H_ + ip)) * W_ + jp0) * OC_ + 2 * q + delta;
    const float off0 = __half2float(orow[0]);
    const float off1 = __half2float(orow[OC_]);

    float c0 = off0 + (float)i;
    float c1 = off1 + (float)j;
    c0 = fminf(fmaxf(c0, 0.f), (float)(W_ - 1));
    c1 = fminf(fmaxf(c1, 0.f), (float)(H_ - 1));

    const float fl0 = floorf(c0), fl1 = floorf(c1);
    const int lt0 = (int)fl0,       lt1 = (int)fl1;
    const int rb0 = (int)ceilf(c0), rb1 = (int)ceilf(c1);
    const float fr0 = c0 - fl0, fr1 = c1 - fl1;

    const float* xp = x + (size_t)b * (H_ * W_ * C_) + q;
    const float v_lt = __ldg(xp + (size_t)(lt0 * W_ + lt1) * C_);
    const float v_rb = __ldg(xp + (size_t)(rb0 * W_ + rb1) * C_);
    const float v_lb = __ldg(xp + (size_t)(lt0 * W_ + rb1) * C_);
    const float v_rt = __ldg(xp + (size_t)(rb0 * W_ + lt1) * C_);

    const float vt = v_lt + (v_rt - v_lt) * fr0;
    const float vb = v_lb + (v_rb - v_lb) * fr0;
    return vt + (vb - vt) * fr1;
}

__global__ void sample_kernel(const float* __restrict__ x,
                              float* __restrict__ out) {
    const int q    = threadIdx.x;
    const int bij0 = blockIdx.x * 2;          // even j
    const int j0   = bij0 & 127;
    const int i    = (bij0 >> 7) & 127;
    const int b    = bij0 >> 14;

    const float r0 = sample_one(x, b, i, j0,     q);
    const float r1 = sample_one(x, b, i, j0 + 1, q);
    out[(size_t)bij0 * C_ + q]       = r0;
    out[(size_t)(bij0 + 1) * C_ + q] = r1;
}

// ---------------- launch ----------------
extern "C" void kernel_launch(void* const* d_in, const int* in_sizes, int n_in,
                              void* d_out, int out_size) {
    const float* x    = (const float*)d_in[0];   // (8,128,128,256) f32
    const float* wgt  = (const float*)d_in[1];   // (3,3,256,512)  f32
    const float* bias = (const float*)d_in[2];   // (512,)         f32
    float* out = (float*)d_out;

    conv_x_f16<<<16384, 256>>>(x);
    conv_w_f16<<<576, 256>>>(wgt);

    cudaFuncSetAttribute(conv_hmma,
                         cudaFuncAttributeMaxDynamicSharedMemorySize, SMEM_BYTES);
    conv_hmma<<<dim3(4, 1024), 256, SMEM_BYTES>>>(bias);

    sample_kernel<<<(B_ * H_ * W_) / 2, 256>>>(x, out);
}